// round 15
// baseline (speedup 1.0000x reference)
#include <cuda_runtime.h>
#include <math.h>

#define BATCH 16
#define FH 192
#define FW 192
#define NA 9
#define NPI (FH*FW*NA)      /* 331776 anchors per image */
#define NPI4 (NPI/4)        /* 82944 */
#define PRE 6000
#define POST 1000
#define CAP 8192            /* candidate capacity per image (power of two for bitonic) */
#define HB 65536            /* histogram buckets = top 16 bits of fp32 score */
#define NMSW 128            /* NMS window size (4 mask words) */

// dynamic smem layout for the fused kernel
#define SM_BOXES 0                       /* float4[PRE]  96000 */
#define SM_KEYS  96000                   /* u64[CAP]     65536 (reused as sarea) */
#define SM_DYN   (96000 + 65536)         /* 161536 */

// ---------------- device scratch (no allocations allowed) ----------------
__device__ unsigned int       g_hist[BATCH * HB];        // 4 MB (zeroed by k_collect each pass)
__device__ unsigned int       g_cnt[BATCH];
__device__ int                g_thresh[BATCH];
__device__ unsigned long long g_keys[BATCH * CAP];       // 1 MB

// ---------------- kernel 1: score-bit histogram per image -----------------
// grid (81, BATCH) x 256: exactly 4 float4 per thread, batched for MLP.
__global__ void k_hist(const float* __restrict__ scores) {
    int b = blockIdx.y;
    const float4* s4 = (const float4*)(scores + (size_t)b * NPI);
    unsigned* h = g_hist + (size_t)b * HB;
    int i = blockIdx.x * blockDim.x + threadIdx.x;
    int step = gridDim.x * blockDim.x;                  // 20736 = NPI4/4
    float4 v0 = s4[i];
    float4 v1 = s4[i + step];
    float4 v2 = s4[i + 2 * step];
    float4 v3 = s4[i + 3 * step];
    atomicAdd(&h[__float_as_uint(v0.x) >> 16], 1u);
    atomicAdd(&h[__float_as_uint(v0.y) >> 16], 1u);
    atomicAdd(&h[__float_as_uint(v0.z) >> 16], 1u);
    atomicAdd(&h[__float_as_uint(v0.w) >> 16], 1u);
    atomicAdd(&h[__float_as_uint(v1.x) >> 16], 1u);
    atomicAdd(&h[__float_as_uint(v1.y) >> 16], 1u);
    atomicAdd(&h[__float_as_uint(v1.z) >> 16], 1u);
    atomicAdd(&h[__float_as_uint(v1.w) >> 16], 1u);
    atomicAdd(&h[__float_as_uint(v2.x) >> 16], 1u);
    atomicAdd(&h[__float_as_uint(v2.y) >> 16], 1u);
    atomicAdd(&h[__float_as_uint(v2.z) >> 16], 1u);
    atomicAdd(&h[__float_as_uint(v2.w) >> 16], 1u);
    atomicAdd(&h[__float_as_uint(v3.x) >> 16], 1u);
    atomicAdd(&h[__float_as_uint(v3.y) >> 16], 1u);
    atomicAdd(&h[__float_as_uint(v3.z) >> 16], 1u);
    atomicAdd(&h[__float_as_uint(v3.w) >> 16], 1u);
}

// ---------------- kernel 2: per-image threshold bucket --------------------
// Largest bucket T such that count(bucket >= T) >= PRE; resets g_cnt.
__global__ void k_thresh() {
    int b = blockIdx.x;
    int t = threadIdx.x;               // 256 threads, each sums a 256-bucket chunk
    __shared__ unsigned csum[256];
    __shared__ unsigned sbuf[256];
    __shared__ unsigned sfin[256];
    __shared__ int s_chunk;
    __shared__ unsigned s_above;
    const unsigned* h = g_hist + (size_t)b * HB;
    int base = t * 256;
    unsigned s = 0;
    for (int i = 0; i < 256; i++) s += h[base + i];
    csum[t] = s;
    __syncthreads();
    if (t == 0) {
        unsigned cum = 0;
        int c = 255;
        for (; c >= 0; c--) {
            if (cum + csum[c] >= PRE) break;
            cum += csum[c];
        }
        s_chunk = c;
        s_above = cum;                 // count strictly above chunk c
        g_cnt[b] = 0u;                 // reset candidate counter for k_collect
    }
    __syncthreads();
    int c = s_chunk;
    unsigned above = s_above;
    sbuf[t] = h[c * 256 + t];
    __syncthreads();
    // inclusive suffix sum (Hillis-Steele)
    for (int d = 1; d < 256; d <<= 1) {
        unsigned v = (t + d < 256) ? sbuf[t + d] : 0u;
        __syncthreads();
        sbuf[t] += v;
        __syncthreads();
    }
    sfin[t] = sbuf[t];
    __syncthreads();
    // largest index i with suffix(i)+above >= PRE (suffix is non-increasing)
    bool ok = (sfin[t] + above >= PRE);
    bool next_ok = (t < 255) ? (sfin[t + 1] + above >= PRE) : false;
    if (ok && !next_ok) g_thresh[b] = c * 256 + t;
}

// ---------------- kernel 3: collect candidate keys + zero histogram -------
// key = (score_bits << 32) | (~idx): descending sort => score desc, then idx asc
// (matches lax.top_k stable tie-breaking exactly).
__global__ void k_collect(const float* __restrict__ scores) {
    int b = blockIdx.y;
    const float4* s4 = (const float4*)(scores + (size_t)b * NPI);
    int T = g_thresh[b];
    int i = blockIdx.x * blockDim.x + threadIdx.x;
    int step = gridDim.x * blockDim.x;                  // 20736
    float4 v[4];
    v[0] = s4[i]; v[1] = s4[i + step]; v[2] = s4[i + 2 * step];
    v[3] = s4[i + 3 * step];
#pragma unroll
    for (int q = 0; q < 4; q++) {
        unsigned bw[4] = {__float_as_uint(v[q].x), __float_as_uint(v[q].y),
                          __float_as_uint(v[q].z), __float_as_uint(v[q].w)};
#pragma unroll
        for (int c = 0; c < 4; c++) {
            if ((int)(bw[c] >> 16) >= T) {
                unsigned pos = atomicAdd(&g_cnt[b], 1u);
                if (pos < CAP) {
                    unsigned idx = 4u * (unsigned)(i + q * step) + (unsigned)c;
                    g_keys[(size_t)b * CAP + pos] =
                        ((unsigned long long)bw[c] << 32) |
                        (unsigned long long)(0xFFFFFFFFu - idx);
                }
            }
        }
    }
    // zero histogram for next replay
    unsigned* h = g_hist + (size_t)b * HB;
    for (int j = i; j < HB; j += step) h[j] = 0u;
}

// ---------------- suppression decision (identical everywhere) -------------
// suppress <=> __fdiv_rn(inter, denom) > 0.7f; banded multiply gives the
// exact answer outside a +-7e-5 relative band (>> 1ulp of mul/div), rare
// exact fdiv fallback inside the band.
__device__ __forceinline__ bool iou_sup(float4 bi, float ai, float4 bj, float aj) {
    float yy1 = fmaxf(bi.x, bj.x);
    float xx1 = fmaxf(bi.y, bj.y);
    float yy2 = fminf(bi.z, bj.z);
    float xx2 = fminf(bi.w, bj.w);
    float ih = fmaxf(__fsub_rn(yy2, yy1), 0.f);
    float iw = fmaxf(__fsub_rn(xx2, xx1), 0.f);
    float inter = __fmul_rn(ih, iw);
    float denom = __fadd_rn(__fsub_rn(__fadd_rn(ai, aj), inter), 1e-8f);
    if (inter > __fmul_rn(denom, 0.7000500f)) return true;
    if (inter < __fmul_rn(denom, 0.6999500f)) return false;
    return __fdiv_rn(inter, denom) > 0.7f;
}

// early-exit variant for long prefilter loops; EXACTLY equivalent:
// if ih<=0 or iw<=0, the full version computes inter==0 and returns false
// (denom >= 1e-8 > 0 makes both banded branches take the false path).
__device__ __forceinline__ bool iou_sup_fast(float4 bi, float ai, float4 bj, float aj) {
    float ih = __fsub_rn(fminf(bi.z, bj.z), fmaxf(bi.x, bj.x));
    if (ih <= 0.f) return false;
    float iw = __fsub_rn(fminf(bi.w, bj.w), fmaxf(bi.y, bj.y));
    if (iw <= 0.f) return false;
    float inter = __fmul_rn(ih, iw);
    float denom = __fadd_rn(__fsub_rn(__fadd_rn(ai, aj), inter), 1e-8f);
    if (inter > __fmul_rn(denom, 0.7000500f)) return true;
    if (inter < __fmul_rn(denom, 0.6999500f)) return false;
    return __fdiv_rn(inter, denom) > 0.7f;
}

__device__ __forceinline__ float box_area(float4 v) {
    return __fmul_rn(fmaxf(__fsub_rn(v.z, v.x), 0.f),
                     fmaxf(__fsub_rn(v.w, v.y), 0.f));
}

// ---------------- kernel 4: fused sort + decode + lazy-window NMS ---------
// One block per image. Keys sorted in smem; boxes decoded into smem (no
// global round trip); keys region recycled as the area array; lazy-window
// NMS reads candidates straight from the smem box array (no staging).
__global__ __launch_bounds__(1024) void k_fused(
        const float* __restrict__ deltas, const float* __restrict__ banch,
        float* __restrict__ out) {
    extern __shared__ unsigned char dyn[];
    float4* boxes = (float4*)(dyn + SM_BOXES);
    unsigned long long* sk = (unsigned long long*)(dyn + SM_KEYS);
    float* sarea = (float*)(dyn + SM_KEYS);          // alias, used after sort

    __shared__ float4 selb[POST];        // 16000 selected boxes
    __shared__ float  sela[POST];        //  4000
    __shared__ uint4  sup4[NMSW];        //  2048 in-window matrix
    __shared__ unsigned pdm[2][4];
    __shared__ unsigned short spos[NMSW];
    __shared__ int s_nsel;
    __shared__ float sbase[NA * 4];
    unsigned* sup = (unsigned*)sup4;

    int b = blockIdx.x, tid = threadIdx.x, bs = blockDim.x;

    // ---- load keys ----
    unsigned cnt = g_cnt[b];
    if (cnt > CAP) cnt = CAP;
    for (int i = tid; i < CAP; i += bs)
        sk[i] = ((unsigned)i < cnt) ? g_keys[(size_t)b * CAP + i] : 0ull;
    if (tid < NA * 4) sbase[tid] = banch[tid];
    __syncthreads();

    // ---- bitonic sort, descending (register-blocked 8/thread) ----
    for (int k2 = 2; k2 <= CAP; k2 <<= 1) {
        for (int j = k2 >> 1; j >= 8; j >>= 1) {
            for (int i = tid; i < CAP; i += bs) {
                int ixj = i ^ j;
                if (ixj > i) {
                    unsigned long long a = sk[i], c = sk[ixj];
                    bool desc = ((i & k2) == 0);
                    if (desc ? (a < c) : (a > c)) { sk[i] = c; sk[ixj] = a; }
                }
            }
            __syncthreads();
        }
        {
            int base = tid * 8;                  // bs*8 == CAP exactly
            unsigned long long v[8];
#pragma unroll
            for (int q = 0; q < 8; q++) v[q] = sk[base + q];
#pragma unroll
            for (int j = 4; j >= 1; j >>= 1) {
                if (j < k2) {
#pragma unroll
                    for (int idx = 0; idx < 8; idx++) {
                        if ((idx & j) == 0) {
                            int ix2 = idx | j;
                            bool desc = (((base + idx) & k2) == 0);
                            unsigned long long a = v[idx], c = v[ix2];
                            if (desc ? (a < c) : (a > c)) { v[idx] = c; v[ix2] = a; }
                        }
                    }
                }
            }
#pragma unroll
            for (int q = 0; q < 8; q++) sk[base + q] = v[q];
            __syncthreads();
        }
    }

    // ---- decode top PRE boxes into smem (strict non-fused fp32) ----
    for (int p = tid; p < PRE; p += bs) {
        unsigned long long key = sk[p];
        unsigned idx = 0xFFFFFFFFu - (unsigned)(key & 0xFFFFFFFFull);
        int a = idx % NA;
        int cell = idx / NA;
        int x = cell % FW;
        int y = cell / FW;
        float gy = __fdiv_rn((float)y + 0.5f, (float)FH);
        float gx = __fdiv_rn((float)x + 0.5f, (float)FW);
        float a0 = fminf(fmaxf(__fadd_rn(gy, sbase[a * 4 + 0]), 0.f), 1.f);
        float a1 = fminf(fmaxf(__fadd_rn(gx, sbase[a * 4 + 1]), 0.f), 1.f);
        float a2 = fminf(fmaxf(__fadd_rn(gy, sbase[a * 4 + 2]), 0.f), 1.f);
        float a3 = fminf(fmaxf(__fadd_rn(gx, sbase[a * 4 + 3]), 0.f), 1.f);
        const float* dp =
            deltas + ((((size_t)b * FH + y) * FW + x) * NA + a) * 4;
        float d0 = __fmul_rn(dp[0], 0.1f);
        float d1 = __fmul_rn(dp[1], 0.1f);
        float d2 = __fmul_rn(dp[2], 0.2f);
        float d3 = __fmul_rn(dp[3], 0.2f);
        float ah = __fsub_rn(a2, a0), aw = __fsub_rn(a3, a1);
        float acy = __fadd_rn(a0, __fmul_rn(0.5f, ah));
        float acx = __fadd_rn(a1, __fmul_rn(0.5f, aw));
        float eh = (float)exp((double)d2);   // correctly-rounded fp32 exp
        float ew = (float)exp((double)d3);
        float h = __fmul_rn(eh, ah);
        float w = __fmul_rn(ew, aw);
        float cy = __fadd_rn(__fmul_rn(d0, ah), acy);
        float cx = __fadd_rn(__fmul_rn(d1, aw), acx);
        float4 box;
        box.x = fminf(fmaxf(__fsub_rn(cy, __fmul_rn(0.5f, h)), 0.f), 1.f);
        box.y = fminf(fmaxf(__fsub_rn(cx, __fmul_rn(0.5f, w)), 0.f), 1.f);
        box.z = fminf(fmaxf(__fadd_rn(cy, __fmul_rn(0.5f, h)), 0.f), 1.f);
        box.w = fminf(fmaxf(__fadd_rn(cx, __fmul_rn(0.5f, w)), 0.f), 1.f);
        boxes[p] = box;
    }
    __syncthreads();            // all sk reads done before sarea overwrites
    for (int p = tid; p < PRE; p += bs) sarea[p] = box_area(boxes[p]);
    if (tid < 4) pdm[0][tid] = 0u;
    __syncthreads();

    // ---- lazy-window NMS ----
    float4* orow4 = (float4*)(out + (size_t)b * POST * 4);
    int k = 0, pos = 0, cur = 0;
    while (k < POST && pos < PRE) {
        int w = PRE - pos; if (w > NMSW) w = NMSW;
        int nxt = cur ^ 1;
        int npos = pos + w;
        int wn = PRE - npos; if (wn > NMSW) wn = NMSW;   // may be <= 0

        // ---- matrix phase (tid<512) + zero pdm[nxt] (tail threads) ----
        if (tid < 512) {
            int p = tid >> 2, wd = tid & 3;
            unsigned m = 0;
            int jb = wd << 5;
            bool prow_dead = (pdm[cur][p >> 5] >> (p & 31)) & 1u;
            if (p < w && jb + 31 > p && !prow_dead) {
                float4 bp = boxes[pos + p];
                float ap = sarea[pos + p];
#pragma unroll 8
                for (int t = 0; t < 32; t++) {
                    int q = jb + t;
                    if (q > p && q < w &&
                        iou_sup(bp, ap, boxes[pos + q], sarea[pos + q]))
                        m |= 1u << t;
                }
            }
            sup[tid] = m;
        } else if (tid >= 1020) {
            pdm[nxt][tid - 1020] = 0u;
        }
        __syncthreads();

        // ---- parallel phase: warp0 chain | warps 1-31 prefilter next ----
        if (tid == 0) {
            unsigned dead[4];
#pragma unroll
            for (int wd = 0; wd < 4; wd++) {
                int hi = w - (wd << 5);
                unsigned valid = (hi >= 32) ? 0xffffffffu
                                            : (hi > 0 ? ((1u << hi) - 1u) : 0u);
                dead[wd] = pdm[cur][wd] | ~valid;
            }
            int nsel = 0;
            int lim = POST - k; if (lim > w) lim = w;
            while (nsel < lim) {
                int p = -1;
#pragma unroll
                for (int wd = 0; wd < 4; wd++) {
                    unsigned a = ~dead[wd];
                    if (p < 0 && a) p = (wd << 5) + __ffs(a) - 1;
                }
                if (p < 0) break;
                spos[nsel++] = (unsigned short)p;
                dead[p >> 5] |= 1u << (p & 31);
                if (nsel >= lim) break;
                uint4 r = sup4[p];
                dead[0] |= r.x; dead[1] |= r.y;
                dead[2] |= r.z; dead[3] |= r.w;
            }
            s_nsel = nsel;
        } else if (tid >= 32 && wn > 0 && k > 0) {
            int worker = tid - 32;               // 0..991; use 896 = 128*7
            if (worker < 896) {
                int j = worker & 127, sub = worker >> 7;   // sub 0..6
                if (j < wn) {
                    float4 bj = boxes[npos + j];
                    float aj = sarea[npos + j];
                    for (int s = sub; s < k; s += 7) {
                        if (iou_sup_fast(selb[s], sela[s], bj, aj)) {
                            atomicOr(&pdm[nxt][j >> 5], 1u << (j & 31));
                            break;
                        }
                    }
                }
            }
        }
        __syncthreads();
        int nsel = s_nsel;

        // ---- append selections + incremental prefilter vs new sels ----
        if (tid < nsel) {
            int p = spos[tid];
            float4 v = boxes[pos + p];
            selb[k + tid] = v;
            sela[k + tid] = sarea[pos + p];
            orow4[k + tid] = v;
        }
        if (wn > 0 && nsel > 0) {
            int j = tid & 127, sub = tid >> 7;       // 8 threads per candidate
            if (j < wn && !((pdm[nxt][j >> 5] >> (j & 31)) & 1u)) {
                float4 bj = boxes[npos + j];
                float aj = sarea[npos + j];
                for (int s = sub; s < nsel; s += 8) {
                    int ps = pos + spos[s];
                    if (iou_sup_fast(boxes[ps], sarea[ps], bj, aj)) {
                        atomicOr(&pdm[nxt][j >> 5], 1u << (j & 31));
                        break;
                    }
                }
            }
        }
        k += nsel;
        pos = npos;
        cur = nxt;
        __syncthreads();
    }
    // zero-pad remaining outputs (reference pads with zeros)
    for (int idx = k * 4 + tid; idx < POST * 4; idx += bs)
        out[(size_t)b * POST * 4 + idx] = 0.0f;
}

// ---------------- launch ---------------------------------------------------
extern "C" void kernel_launch(void* const* d_in, const int* in_sizes, int n_in,
                              void* d_out, int out_size) {
    const float* deltas = (const float*)d_in[0];   // (16,192,192,36)
    const float* scores = (const float*)d_in[1];   // (16,192,192,9)
    const float* banch  = (const float*)d_in[2];   // (9,4)
    float* out = (float*)d_out;                    // (16,1000,4)

    cudaFuncSetAttribute(k_fused,
                         cudaFuncAttributeMaxDynamicSharedMemorySize, SM_DYN);

    dim3 grid2(81, BATCH);                         // exactly 4 float4/thread
    k_hist<<<grid2, 256>>>(scores);
    k_thresh<<<BATCH, 256>>>();
    k_collect<<<grid2, 256>>>(scores);
    k_fused<<<BATCH, 1024, SM_DYN>>>(deltas, banch, out);
}